// round 16
// baseline (speedup 1.0000x reference)
#include <cuda_runtime.h>
#include <cstdint>

// ---------------- scratch (device globals; no allocations allowed) ----------------
__device__ float g_h1[46099200];   // (128,150,49,49)
__device__ float g_h2[46099200];   // (128,150,49,49)
__device__ float g_sT[23970816];   // (128,51*51,72)  trans -> softmax in-place
__device__ float g_rew[332928];    // (128,51*51)
__device__ float g_q[2458624];     // (128,49,49,8)
__device__ float g_wp[360448];     // pre-permuted tf32 weights (conv1/conv2/trans)

__device__ __forceinline__ unsigned int f2tf32(float v) {
    unsigned int u;
    asm("cvt.rna.tf32.f32 %0, %1;" : "=r"(u) : "f"(v));
    return u;
}

__device__ __forceinline__ void mma_tf32(float* c, unsigned int a0, unsigned int a1,
                                         unsigned int a2, unsigned int a3,
                                         unsigned int b0, unsigned int b1) {
    asm volatile("mma.sync.aligned.m16n8k8.row.col.f32.tf32.tf32.f32 "
                 "{%0,%1,%2,%3}, {%4,%5,%6,%7}, {%8,%9}, {%0,%1,%2,%3};"
                 : "+f"(c[0]), "+f"(c[1]), "+f"(c[2]), "+f"(c[3])
                 : "r"(a0), "r"(a1), "r"(a2), "r"(a3), "r"(b0), "r"(b1));
}

// =================================================================================
// Weight pre-permutation: gmem -> fragment-ordered tf32 image.
// Flat layout: [ot][ch][tap][mt(5)][grp(8)][tig(4)][j(4)]
//   j=0:(oc=16mt+grp, ic=tig)  j=1:(oc+8, tig)  j=2:(oc, tig+4)  j=3:(oc+8, tig+4)
// epi: trans+reward fusion (oc 72 = reward weights, oc>72 = 0).
// =================================================================================
__global__ void prep_kernel(const float* __restrict__ w, const float* __restrict__ w2,
                            float* __restrict__ dst, int IC, int OC, int CH, int epi, int total)
{
    const int idx = blockIdx.x * 256 + threadIdx.x;
    if (idx >= total) return;
    const int j   = idx & 3;
    const int tig = (idx >> 2) & 3;
    const int grp = (idx >> 4) & 7;
    const int r1  = idx >> 7;
    const int mt  = r1 % 5;
    const int r2  = r1 / 5;
    const int tap = r2 % 9;
    const int r3  = r2 / 9;
    const int ch  = r3 % CH;
    const int ot  = r3 / CH;

    const int oc  = ot * 80 + mt * 16 + grp + (j & 1) * 8;
    const int ick = tig + (j >> 1) * 4;
    const int ic  = ch * 8 + ick;

    float v = 0.f;
    if (ic < IC) {
        if (epi) {
            if (oc == 72)      v = w2[ic * 9 + tap];
            else if (oc < 72)  v = w[((size_t)oc * IC + ic) * 9 + tap];
        } else if (oc < OC) {
            v = w[((size_t)oc * IC + ic) * 9 + tap];
        }
    }
    reinterpret_cast<unsigned int*>(dst)[idx] = f2tf32(v);
}

// =================================================================================
// Implicit-GEMM 3x3 conv, mma.sync tf32.  320 threads = 10 warps:
//   warp = (mt 0..4) x (n-half 0..1); each warp m16 x n64 -> c[8][4] (32 regs).
// K per chunk = 8 ic x 9 taps.  A fragments 1 LDS.128/tap, B 1 LDS.64/mma.
// Software-pipelined X staging: chunk ch+1's LDGs issued before chunk ch's MMA
// loop (consumed next iteration) -> DRAM latency hidden behind compute.
// EPI=0: NCHW out (+bias, relu).  EPI=1: sT pixel-major; oc==72 -> reward.
// =================================================================================
template<int IC, int PAD, int EPI, bool RELU>
__global__ void __launch_bounds__(320, 2)
conv_mma2(const float* __restrict__ in, const float* __restrict__ wp,
          const float* __restrict__ bias, float* __restrict__ out,
          float* __restrict__ rew, const int OC)
{
    constexpr int HW  = 47 + 2 * PAD;
    constexpr int NPX = HW * HW;
    constexpr int CH  = (IC + 7) / 8;
    constexpr int XSTR = 338;                      // float2 row stride per tig-slot
    constexpr int NSLOT = 9;                       // ceil(2688/320)

    __shared__ float4 smem4[2692];                 // 10768 floats (~43KB)
    float* smem_all = reinterpret_cast<float*>(smem4);
    float2* XP2 = reinterpret_cast<float2*>(smem_all);           // acts: 4*338 float2
    float*  APf = smem_all + 2704;                               // weights: 5760 floats
    const float4* AP4 = reinterpret_cast<const float4*>(APf);

    const int tid  = threadIdx.x;
    const int lane = tid & 31;
    const int warp = tid >> 5;          // 0..9
    const int mt   = warp >> 1;         // m-tile 0..4
    const int nh   = warp & 1;          // n-half 0..1
    const int tig  = lane & 3;
    const int grp  = lane >> 2;

    const int n0  = blockIdx.x * 128;
    const int ot  = blockIdx.y;
    const int oc0 = ot * 80;
    const int b   = blockIdx.z;
    const int ybase = n0 / HW;
    const float* inb = in + (size_t)b * IC * 2401;
    const float* wpc = wp + (size_t)ot * CH * 5760;

    // ---- hoisted staging slots: thread handles elements tid, tid+320, ... of 2688 ----
    uint32_t smoff[NSLOT];
    int      goff [NSLOT];
    int      icks [NSLOT];
    uint32_t vmask = 0;
#pragma unroll
    for (int s = 0; s < NSLOT; ++s) {
        const int e = tid + s * 320;
        smoff[s] = 0; goff[s] = 0; icks[s] = 0;
        if (e < 2688) {
            const int ick = e / 336;
            const int rem = e - ick * 336;
            const int r  = rem / 56;
            const int cc = rem - r * 56;
            const int iy = ybase - PAD + r;
            const int ix = cc - PAD;
            smoff[s] = (((uint32_t)(ick & 3) * XSTR + rem) << 1) + (ick >> 2);
            icks[s]  = ick;
            if (iy >= 0 && iy < 49 && ix >= 0 && ix < 49) {
                goff[s] = ick * 2401 + iy * 49 + ix;
                vmask |= (1u << s);
            }
        }
    }

    // per-ntile B spatial base for this warp's n-half (pixel (nh*8+nt)*8+grp)
    int basent[8];
#pragma unroll
    for (int nt = 0; nt < 8; ++nt) {
        int n = n0 + (nh * 8 + nt) * 8 + grp;
        if (n > NPX - 1) n = NPX - 1;
        const int y = n / HW, x = n - y * HW;
        basent[nt] = (y - ybase) * 56 + x;
    }

    float c[8][4];
#pragma unroll
    for (int nt = 0; nt < 8; ++nt)
#pragma unroll
        for (int j = 0; j < 4; ++j) c[nt][j] = 0.f;

    unsigned int* smem_u = reinterpret_cast<unsigned int*>(smem_all);

    // ---- prologue: prefetch chunk 0's X into registers ----
    float xr[NSLOT];
#pragma unroll
    for (int s = 0; s < NSLOT; ++s) {
        const bool ok = ((vmask >> s) & 1u) && (icks[s] < IC);
        xr[s] = ok ? __ldg(inb + goff[s]) : 0.f;
    }

    for (int ch = 0; ch < CH; ++ch) {
        __syncthreads();
        // ---- commit prefetched X to smem ----
#pragma unroll
        for (int s = 0; s < NSLOT; ++s)
            if (tid + s * 320 < 2688) smem_u[smoff[s]] = f2tf32(xr[s]);
        // ---- stage A: straight float4 copy of pre-permuted weights ----
        {
            const float4* src = reinterpret_cast<const float4*>(wpc + (size_t)ch * 5760);
            float4* dst = reinterpret_cast<float4*>(APf);
            for (int i = tid; i < 1440; i += 320) dst[i] = src[i];
        }
        // ---- issue next chunk's X LDGs (consumed next iteration) ----
        if (ch + 1 < CH) {
            const float* src = inb + (ch + 1) * 8 * 2401;
            const int icbase = (ch + 1) * 8;
#pragma unroll
            for (int s = 0; s < NSLOT; ++s) {
                const bool ok = ((vmask >> s) & 1u) && (icbase + icks[s] < IC);
                xr[s] = ok ? __ldg(src + goff[s]) : 0.f;
            }
        }
        __syncthreads();

        // ---- mma loop ----
#pragma unroll
        for (int tap = 0; tap < 9; ++tap) {
            const int ky = tap / 3, kx = tap - ky * 3;
            const int tapoff = ky * 56 + kx;
            const float4 a = AP4[((tap * 5 + mt) * 8 + grp) * 4 + tig];
            const unsigned int a0 = __float_as_uint(a.x);
            const unsigned int a1 = __float_as_uint(a.y);
            const unsigned int a2 = __float_as_uint(a.z);
            const unsigned int a3 = __float_as_uint(a.w);
            const float2* xb = XP2 + tig * XSTR + tapoff;
#pragma unroll
            for (int nt = 0; nt < 8; ++nt) {
                const float2 bv = xb[basent[nt]];
                mma_tf32(c[nt], a0, a1, a2, a3, __float_as_uint(bv.x), __float_as_uint(bv.y));
            }
        }
    }

    // ---- epilogue: regs -> smem transpose -> coalesced gmem ----
    __syncthreads();
#pragma unroll
    for (int nt = 0; nt < 8; ++nt)
#pragma unroll
        for (int j = 0; j < 4; ++j) {
            const int rl = mt * 16 + grp + 8 * (j >> 1);
            const int pl = (nh * 8 + nt) * 8 + tig * 2 + (j & 1);
            if (EPI == 0) smem_all[rl * 132 + pl] = c[nt][j];
            else          smem_all[pl * 84 + rl] = c[nt][j];
        }
    __syncthreads();

    if (EPI == 0) {
        for (int i = tid; i < 80 * 128; i += 320) {
            const int ocl = i >> 7, px = i & 127;
            const int oc = oc0 + ocl, pg = n0 + px;
            if (oc < OC && pg < NPX) {
                float v = smem_all[ocl * 132 + px] + bias[oc];
                if (RELU) v = fmaxf(v, 0.f);
                out[(size_t)(b * OC + oc) * NPX + pg] = v;
            }
        }
    } else {
        for (int i = tid; i < 128 * 73; i += 320) {
            const int px = i / 73, ocl = i - px * 73;
            const int pg = n0 + px;
            if (pg < NPX) {
                const float v = smem_all[px * 84 + ocl];
                if (ocl < 72)       out[((size_t)b * 2601 + pg) * 72 + ocl] = v;
                else                rew[(size_t)b * 2601 + pg] = v;
            }
        }
    }
}

// ---------------- per-pixel softmax over k=9 within each of 8 actions (in place) ----------------
__global__ void softmax_kernel(float* __restrict__ t)
{
    const int idx = blockIdx.x * 256 + threadIdx.x;
    if (idx >= 128 * 2601) return;
    float* p = t + (size_t)idx * 72;
    float a_[72];
    float4* pv = reinterpret_cast<float4*>(p);
#pragma unroll
    for (int i = 0; i < 18; ++i) {
        float4 v = pv[i];
        a_[4 * i] = v.x; a_[4 * i + 1] = v.y; a_[4 * i + 2] = v.z; a_[4 * i + 3] = v.w;
    }
#pragma unroll
    for (int a = 0; a < 8; ++a) {
        const int bs = a * 9;
        float m = a_[bs];
#pragma unroll
        for (int k = 1; k < 9; ++k) m = fmaxf(m, a_[bs + k]);
        float s = 0.f;
#pragma unroll
        for (int k = 0; k < 9; ++k) { float e = expf(a_[bs + k] - m); a_[bs + k] = e; s += e; }
        const float inv = 1.f / s;
#pragma unroll
        for (int k = 0; k < 9; ++k) a_[bs + k] *= inv;
    }
#pragma unroll
    for (int i = 0; i < 18; ++i)
        pv[i] = make_float4(a_[4 * i], a_[4 * i + 1], a_[4 * i + 2], a_[4 * i + 3]);
}

// ---------------- value iteration: 1 CTA per batch, K=30, v in smem, sT in L2 ----------------
// 512 threads: halves the per-thread px sweep depth (latency-bound on sT L2 loads).
__global__ void __launch_bounds__(512)
vi_kernel(const float* __restrict__ sT, const float* __restrict__ rew,
          float* __restrict__ qout)
{
    const int b = blockIdx.x;
    const int tid = threadIdx.x;
    __shared__ float vp[2][53 * 53];
    __shared__ float rs[2601];
    for (int i = tid; i < 53 * 53; i += 512) { vp[0][i] = 0.f; vp[1][i] = 0.f; }
    for (int i = tid; i < 2601; i += 512) rs[i] = rew[(size_t)b * 2601 + i];
    __syncthreads();

    const float* stb = sT + (size_t)b * 2601 * 72;
    int cur = 0;
    for (int it = 0; it < 30; ++it) {
        const bool last = (it == 29);
        for (int px = tid; px < 2601; px += 512) {
            const int y = px / 51, x = px - y * 51;
            const float* vc = &vp[cur][y * 53 + x];
            float vn[9];
#pragma unroll
            for (int ky = 0; ky < 3; ++ky)
#pragma unroll
                for (int kx = 0; kx < 3; ++kx) vn[ky * 3 + kx] = vc[ky * 53 + kx];

            float a_[72];
            const float4* sp = reinterpret_cast<const float4*>(stb + (size_t)px * 72);
#pragma unroll
            for (int i = 0; i < 18; ++i) {
                float4 v = __ldg(&sp[i]);
                a_[4 * i] = v.x; a_[4 * i + 1] = v.y; a_[4 * i + 2] = v.z; a_[4 * i + 3] = v.w;
            }
            const float r = rs[px];
            float vmax = -3.4e38f;
#pragma unroll
            for (int a = 0; a < 8; ++a) {
                float q = r;
#pragma unroll
                for (int k = 0; k < 9; ++k) q += a_[a * 9 + k] * vn[k];
                if (last && y < 49 && x < 49)
                    qout[(((size_t)b * 49 + y) * 49 + x) * 8 + a] = q;
                vmax = fmaxf(vmax, q);
            }
            vp[cur ^ 1][(y + 1) * 53 + (x + 1)] = vmax;
        }
        __syncthreads();
        cur ^= 1;
    }
}

// ---------------- head: per pixel 8 -> relu(150) -> 8, output (B,8,49,49) ----------------
__global__ void head_kernel(const float* __restrict__ q, const float* __restrict__ a1w,
                            const float* __restrict__ a1b, const float* __restrict__ a2w,
                            const float* __restrict__ a2b, float* __restrict__ out)
{
    __shared__ float s1[1200];
    __shared__ float s2[1200];
    __shared__ float sb1[150];
    __shared__ float sb2[8];
    for (int i = threadIdx.x; i < 1200; i += 256) {
        s1[i] = a1w[i];
        const int c = i >> 3, a = i & 7;
        s2[i] = a2w[a * 150 + c];
    }
    for (int i = threadIdx.x; i < 150; i += 256) sb1[i] = a1b[i];
    if (threadIdx.x < 8) sb2[threadIdx.x] = a2b[threadIdx.x];
    __syncthreads();

    const int idx = blockIdx.x * 256 + threadIdx.x;
    if (idx >= 128 * 2401) return;
    const int b = idx / 2401, px = idx - b * 2401;

    const float4* qp = reinterpret_cast<const float4*>(q + (size_t)idx * 8);
    const float4 q0 = qp[0], q1 = qp[1];
    const float qv[8] = { q0.x, q0.y, q0.z, q0.w, q1.x, q1.y, q1.z, q1.w };

    float lg[8];
#pragma unroll
    for (int a = 0; a < 8; ++a) lg[a] = sb2[a];

    for (int c = 0; c < 150; ++c) {
        float m = sb1[c];
#pragma unroll
        for (int a = 0; a < 8; ++a) m += s1[c * 8 + a] * qv[a];
        m = fmaxf(m, 0.f);
#pragma unroll
        for (int a = 0; a < 8; ++a) lg[a] += s2[c * 8 + a] * m;
    }
    float* ob = out + (size_t)b * 8 * 2401 + px;
#pragma unroll
    for (int a = 0; a < 8; ++a) ob[(size_t)a * 2401] = lg[a];
}

// ---------------- launch ----------------
extern "C" void kernel_launch(void* const* d_in, const int* in_sizes, int n_in,
                              void* d_out, int out_size)
{
    const float* grid = (const float*)d_in[0];
    const float* h1w = (const float*)d_in[3];
    const float* h1b = (const float*)d_in[4];
    const float* h2w = (const float*)d_in[5];
    const float* h2b = (const float*)d_in[6];
    const float* rw  = (const float*)d_in[7];
    const float* tw  = (const float*)d_in[8];
    const float* a1w = (const float*)d_in[9];
    const float* a1b = (const float*)d_in[10];
    const float* a2w = (const float*)d_in[11];
    const float* a2b = (const float*)d_in[12];
    float* out = (float*)d_out;

    float *h1, *h2, *sT, *rwb, *qb, *wp;
    cudaGetSymbolAddress((void**)&h1, g_h1);
    cudaGetSymbolAddress((void**)&h2, g_h2);
    cudaGetSymbolAddress((void**)&sT, g_sT);
    cudaGetSymbolAddress((void**)&rwb, g_rew);
    cudaGetSymbolAddress((void**)&qb, g_q);
    cudaGetSymbolAddress((void**)&wp, g_wp);

    // Pre-permute weights into fragment order (tf32).
    prep_kernel<<<(11520 + 255) / 256, 256>>>(h1w, nullptr, wp, 2, 150, 1, 0, 11520);
    prep_kernel<<<(218880 + 255) / 256, 256>>>(h2w, nullptr, wp + 11520, 150, 150, 19, 0, 218880);
    prep_kernel<<<(109440 + 255) / 256, 256>>>(tw, rw, wp + 230400, 150, 73, 19, 1, 109440);

    // conv1: 2->150, pad1, relu
    conv_mma2<2, 1, 0, true><<<dim3(19, 2, 128), 320>>>(grid, wp, h1b, h1, nullptr, 150);
    // conv2: 150->150, pad1, relu
    conv_mma2<150, 1, 0, true><<<dim3(19, 2, 128), 320>>>(h1, wp + 11520, h2b, h2, nullptr, 150);
    // trans (oc 0..71) + reward (oc 72) fused: pad2, pixel-major sT output
    conv_mma2<150, 2, 1, false><<<dim3(21, 1, 128), 320>>>(h2, wp + 230400, nullptr, sT, rwb, 73);
    // softmax over the 9 kernel taps per action (in place on sT)
    softmax_kernel<<<(128 * 2601 + 255) / 256, 256>>>(sT);
    // K=30 value iteration, persistent CTA per batch (512 threads)
    vi_kernel<<<128, 512>>>(sT, rwb, qb);
    // head 8->150->8
    head_kernel<<<(128 * 2401 + 255) / 256, 256>>>(qb, a1w, a1b, a2w, a2b, out);
}